// round 2
// baseline (speedup 1.0000x reference)
#include <cuda_runtime.h>
#include <cuda_fp16.h>
#include <cstdint>

#define T_STEPS 300
#define BATCH   256
#define NIN     128
#define NH      512
#define NOUT    3
#define DTSEC   0.01f
#define ALPHA_N 0.2f

#define Y_SIZE (BATCH * T_STEPS * NOUT)

// ---------------- device scratch (static, allocation-free) ----------------
__device__ uint32_t  g_wrnnp[(NH / 2) * NH];     // packed half2 (k-pair x h)
__device__ uint32_t  g_winp[(NIN / 2) * NH];     // packed half2 (k-pair x h)
__device__ float     g_wout[NH * NOUT];
__device__ __half    g_rpost[2 * BATCH * NH];    // double-buffered activations
__device__ float     g_ypart[(size_t)T_STEPS * 16 * 8 * 16 * 3];  // per-slice y partials

// ---------------- smem layout for step kernel ------------------------------
#define OFF_WP    0
#define OFF_WIP   69632               // 256*68*4
#define OFF_RP    87040               // +64*68*4
#define OFF_AINP  103680              // +16*520*2
#define OFF_YSM   108032              // +16*136*2
#define OFF_MBAR  109568              // +16*24*4
#define SMEM_STEP 109600

__device__ __forceinline__ uint32_t smem_u32(const void* p) {
    uint32_t a;
    asm("{ .reg .u64 t; cvta.to.shared.u64 t, %1; cvt.u32.u64 %0, t; }" : "=r"(a) : "l"(p));
    return a;
}

// ---------------- prep: effective weight packing ---------------------------
__global__ void prep_kernel(const float* __restrict__ w_in, const float* __restrict__ w_in_mask,
                            const float* __restrict__ w_rnn_base, const float* __restrict__ conn,
                            const float* __restrict__ ei, const float* __restrict__ w_out,
                            const float* __restrict__ w_out_mask)
{
    int tid = blockIdx.x * blockDim.x + threadIdx.x;
    int nth = gridDim.x * blockDim.x;

    for (int i = tid; i < (NH / 2) * NH; i += nth) {
        int p = i >> 9, h = i & (NH - 1);
        int k0 = 2 * p, k1 = 2 * p + 1;
        float s0 = ei[k0 * NH + k0];
        float s1 = ei[k1 * NH + k1];
        float v0 = fmaxf(w_rnn_base[k0 * NH + h] * conn[k0 * NH + h], 0.f) * s0;
        float v1 = fmaxf(w_rnn_base[k1 * NH + h] * conn[k1 * NH + h], 0.f) * s1;
        __half2 hv = __floats2half2_rn(v0, v1);
        g_wrnnp[i] = *reinterpret_cast<uint32_t*>(&hv);
    }
    for (int i = tid; i < (NIN / 2) * NH; i += nth) {
        int p = i >> 9, h = i & (NH - 1);
        float v0 = w_in[(2 * p) * NH + h] * w_in_mask[(2 * p) * NH + h];
        float v1 = w_in[(2 * p + 1) * NH + h] * w_in_mask[(2 * p + 1) * NH + h];
        __half2 hv = __floats2half2_rn(v0, v1);
        g_winp[i] = *reinterpret_cast<uint32_t*>(&hv);
    }
    for (int i = tid; i < NH * NOUT; i += nth)
        g_wout[i] = fmaxf(w_out[i] * w_out_mask[i], 0.f);
}

// ---------------- persistent step kernel (cluster of 8 = one batch group) --
__global__ void __launch_bounds__(256, 1) __cluster_dims__(8, 1, 1) step_kernel(
    const float* __restrict__ inp, const float* __restrict__ noise,
    const float* __restrict__ x_init, const float* __restrict__ sx_init,
    const float* __restrict__ su_init,
    const float* __restrict__ a_std, const float* __restrict__ a_stf,
    const float* __restrict__ Uv, const float* __restrict__ dynv,
    const float* __restrict__ b_rnn,
    float* __restrict__ out_x)
{
    extern __shared__ uint8_t smem[];
    uint32_t* wp   = reinterpret_cast<uint32_t*>(smem + OFF_WP);   // [256 kp][68]
    uint32_t* wip  = reinterpret_cast<uint32_t*>(smem + OFF_WIP);  // [64 kp][68]
    __half*   rp   = reinterpret_cast<__half*>(smem + OFF_RP);     // [16][520]
    __half*   ainp = reinterpret_cast<__half*>(smem + OFF_AINP);   // [16][136]
    float*    ysm  = reinterpret_cast<float*>(smem + OFF_YSM);     // [16][8][3]
    uint64_t* mbar = reinterpret_cast<uint64_t*>(smem + OFF_MBAR);

    int grp   = blockIdx.x >> 3;
    int slice = blockIdx.x & 7;
    int b0 = grp * 16;
    int h0 = slice * 64;
    int tid = threadIdx.x;
    int w = tid >> 5, lane = tid & 31;
    int g = lane >> 2, t = lane & 3;

    uint32_t mbar_addr = smem_u32(mbar);
    if (tid == 0)
        asm volatile("mbarrier.init.shared.b64 [%0], 8;" :: "r"(mbar_addr) : "memory");

    // persistent weight slices
    #pragma unroll
    for (int j = 0; j < 64; j++) {
        int idx = tid + j * 256;
        int p = idx >> 6, c = idx & 63;
        wp[p * 68 + c] = g_wrnnp[p * NH + h0 + c];
    }
    #pragma unroll
    for (int j = 0; j < 16; j++) {
        int idx = tid + j * 256;
        int p = idx >> 6, c = idx & 63;
        wip[p * 68 + c] = g_winp[p * NH + h0 + c];
    }

    // cluster sync: peers' mbarriers initialized before any remote arrive
    asm volatile("barrier.cluster.arrive.aligned;" ::: "memory");
    asm volatile("barrier.cluster.wait.aligned;"   ::: "memory");

    // element ownership == mma accumulator layout
    int hb  = h0 + 8 * w + 2 * t;
    int br0 = b0 + g, br1 = b0 + g + 8;

    float as0 = a_std[hb], as1 = a_std[hb + 1];
    float af0 = a_stf[hb], af1 = a_stf[hb + 1];
    float U0  = Uv[hb],    U1  = Uv[hb + 1];
    float dy0 = dynv[hb],  dy1 = dynv[hb + 1];
    float brn0 = b_rnn[hb], brn1 = b_rnn[hb + 1];
    float wo00 = g_wout[hb * 3 + 0], wo01 = g_wout[hb * 3 + 1], wo02 = g_wout[hb * 3 + 2];
    float wo10 = g_wout[(hb + 1) * 3 + 0], wo11 = g_wout[(hb + 1) * 3 + 1], wo12 = g_wout[(hb + 1) * 3 + 2];

    float x0 = x_init[br0 * NH + hb],   x1 = x_init[br0 * NH + hb + 1];
    float x2 = x_init[br1 * NH + hb],   x3 = x_init[br1 * NH + hb + 1];
    float sx0 = sx_init[br0 * NH + hb], sx1 = sx_init[br0 * NH + hb + 1];
    float sx2 = sx_init[br1 * NH + hb], sx3 = sx_init[br1 * NH + hb + 1];
    float su0 = su_init[br0 * NH + hb], su1 = su_init[br0 * NH + hb + 1];
    float su2 = su_init[br1 * NH + hb], su3 = su_init[br1 * NH + hb + 1];

    __half2* rgl = reinterpret_cast<__half2*>(g_rpost);

    // input prefetch assignment: one row of 8 floats per thread
    int irow = tid >> 4, ic0 = (tid & 15) * 8;
    float4 pf0 = *reinterpret_cast<const float4*>(inp + ((size_t)0 * BATCH + b0 + irow) * NIN + ic0);
    float4 pf1 = *reinterpret_cast<const float4*>(inp + ((size_t)0 * BATCH + b0 + irow) * NIN + ic0 + 4);

    for (int ts = 0; ts < T_STEPS; ts++) {
        // ---- phase 1: STP update + x_post + rpost ----
        float xp0, xp1, xp2, xp3;
        {
            float r, sxn, sun;
            r = fmaxf(x0, 0.f);
            sxn = sx0 + (as0 * (1.f - sx0) - DTSEC * su0 * sx0 * r) * dy0;
            sun = su0 + (af0 * (U0 - su0) + DTSEC * U0 * (1.f - su0) * r) * dy0;
            sx0 = fminf(fmaxf(sxn, 0.f), 1.f); su0 = fminf(fmaxf(sun, 0.f), 1.f);
            xp0 = su0 * sx0 * x0;

            r = fmaxf(x1, 0.f);
            sxn = sx1 + (as1 * (1.f - sx1) - DTSEC * su1 * sx1 * r) * dy1;
            sun = su1 + (af1 * (U1 - su1) + DTSEC * U1 * (1.f - su1) * r) * dy1;
            sx1 = fminf(fmaxf(sxn, 0.f), 1.f); su1 = fminf(fmaxf(sun, 0.f), 1.f);
            xp1 = su1 * sx1 * x1;

            r = fmaxf(x2, 0.f);
            sxn = sx2 + (as0 * (1.f - sx2) - DTSEC * su2 * sx2 * r) * dy0;
            sun = su2 + (af0 * (U0 - su2) + DTSEC * U0 * (1.f - su2) * r) * dy0;
            sx2 = fminf(fmaxf(sxn, 0.f), 1.f); su2 = fminf(fmaxf(sun, 0.f), 1.f);
            xp2 = su2 * sx2 * x2;

            r = fmaxf(x3, 0.f);
            sxn = sx3 + (as1 * (1.f - sx3) - DTSEC * su3 * sx3 * r) * dy1;
            sun = su3 + (af1 * (U1 - su3) + DTSEC * U1 * (1.f - su3) * r) * dy1;
            sx3 = fminf(fmaxf(sxn, 0.f), 1.f); su3 = fminf(fmaxf(sun, 0.f), 1.f);
            xp3 = su3 * sx3 * x3;
        }
        int buf = ts & 1;
        rgl[(buf * BATCH * NH + br0 * NH + hb) >> 1] =
            __floats2half2_rn(fmaxf(xp0, 0.f), fmaxf(xp1, 0.f));
        rgl[(buf * BATCH * NH + br1 * NH + hb) >> 1] =
            __floats2half2_rn(fmaxf(xp2, 0.f), fmaxf(xp3, 0.f));

        // ---- stage input tile (prefetched last iteration) into smem fp16 ----
        {
            __half2 h0v = __floats2half2_rn(pf0.x, pf0.y);
            __half2 h1v = __floats2half2_rn(pf0.z, pf0.w);
            __half2 h2v = __floats2half2_rn(pf1.x, pf1.y);
            __half2 h3v = __floats2half2_rn(pf1.z, pf1.w);
            uint4 pk;
            pk.x = *reinterpret_cast<uint32_t*>(&h0v);
            pk.y = *reinterpret_cast<uint32_t*>(&h1v);
            pk.z = *reinterpret_cast<uint32_t*>(&h2v);
            pk.w = *reinterpret_cast<uint32_t*>(&h3v);
            *reinterpret_cast<uint4*>(ainp + irow * 136 + ic0) = pk;
        }

        // ---- noise prefetch (consumed in epilogue, hidden by barrier+mma) ----
        float2 nz0 = *reinterpret_cast<const float2*>(&noise[((size_t)ts * BATCH + br0) * NH + hb]);
        float2 nz1 = *reinterpret_cast<const float2*>(&noise[((size_t)ts * BATCH + br1) * NH + hb]);

        // ---- cluster barrier: 8 remote arrives + local wait ----
        __syncthreads();
        if (tid < 8) {
            uint32_t remote;
            asm volatile("mapa.shared::cluster.u32 %0, %1, %2;"
                         : "=r"(remote) : "r"(mbar_addr), "r"(tid));
            asm volatile("mbarrier.arrive.release.cluster.shared::cluster.b64 _, [%0];"
                         :: "r"(remote) : "memory");
        }
        {
            uint32_t parity = ts & 1;
            uint32_t done = 0;
            while (!done)
                asm volatile("{ .reg .pred p; "
                             "mbarrier.try_wait.parity.acquire.cluster.shared::cta.b64 p, [%1], %2, 0x989680; "
                             "selp.b32 %0, 1, 0, p; }"
                             : "=r"(done) : "r"(mbar_addr), "r"(parity) : "memory");
        }

        // ---- stage rpost [16][512] fp16 from L2 (volatile: skip L1) ----
        {
            const uint4* src = reinterpret_cast<const uint4*>(g_rpost + buf * BATCH * NH);
            #pragma unroll
            for (int j = 0; j < 4; j++) {
                int idx = tid + j * 256;
                int row = idx >> 6, c8 = idx & 63;
                uint4 v;
                asm volatile("ld.volatile.global.v4.u32 {%0,%1,%2,%3}, [%4];"
                             : "=r"(v.x), "=r"(v.y), "=r"(v.z), "=r"(v.w)
                             : "l"(src + (size_t)(b0 + row) * 64 + c8));
                *reinterpret_cast<uint4*>(rp + row * 520 + c8 * 8) = v;
            }
        }
        __syncthreads();

        // ---- prefetch input for next step (hidden under mma) ----
        {
            int tsn = (ts + 1 < T_STEPS) ? ts + 1 : ts;
            const float* ib = inp + ((size_t)tsn * BATCH + b0 + irow) * NIN + ic0;
            pf0 = *reinterpret_cast<const float4*>(ib);
            pf1 = *reinterpret_cast<const float4*>(ib + 4);
        }

        // ---- mma: C[16x8] = ainp[16x128]@Win + rpost[16x512]@Wrnn (2 chains) ----
        float e0 = 0.f, e1 = 0.f, e2 = 0.f, e3 = 0.f;
        float f0 = 0.f, f1 = 0.f, f2 = 0.f, f3 = 0.f;
        #pragma unroll
        for (int kk = 0; kk < 8; kk++) {
            int k0 = kk * 16;
            uint32_t a0 = *reinterpret_cast<const uint32_t*>(ainp + g * 136 + k0 + 2 * t);
            uint32_t a1 = *reinterpret_cast<const uint32_t*>(ainp + (g + 8) * 136 + k0 + 2 * t);
            uint32_t a2 = *reinterpret_cast<const uint32_t*>(ainp + g * 136 + k0 + 8 + 2 * t);
            uint32_t a3 = *reinterpret_cast<const uint32_t*>(ainp + (g + 8) * 136 + k0 + 8 + 2 * t);
            uint32_t b0r = wip[(kk * 8 + t) * 68 + 8 * w + g];
            uint32_t b1r = wip[(kk * 8 + t + 4) * 68 + 8 * w + g];
            if (kk & 1)
                asm volatile("mma.sync.aligned.m16n8k16.row.col.f32.f16.f16.f32 "
                             "{%0,%1,%2,%3}, {%4,%5,%6,%7}, {%8,%9}, {%0,%1,%2,%3};"
                             : "+f"(f0), "+f"(f1), "+f"(f2), "+f"(f3)
                             : "r"(a0), "r"(a1), "r"(a2), "r"(a3), "r"(b0r), "r"(b1r));
            else
                asm volatile("mma.sync.aligned.m16n8k16.row.col.f32.f16.f16.f32 "
                             "{%0,%1,%2,%3}, {%4,%5,%6,%7}, {%8,%9}, {%0,%1,%2,%3};"
                             : "+f"(e0), "+f"(e1), "+f"(e2), "+f"(e3)
                             : "r"(a0), "r"(a1), "r"(a2), "r"(a3), "r"(b0r), "r"(b1r));
        }
        #pragma unroll
        for (int kk = 0; kk < 32; kk++) {
            int k0 = kk * 16;
            uint32_t a0 = *reinterpret_cast<const uint32_t*>(rp + g * 520 + k0 + 2 * t);
            uint32_t a1 = *reinterpret_cast<const uint32_t*>(rp + (g + 8) * 520 + k0 + 2 * t);
            uint32_t a2 = *reinterpret_cast<const uint32_t*>(rp + g * 520 + k0 + 8 + 2 * t);
            uint32_t a3 = *reinterpret_cast<const uint32_t*>(rp + (g + 8) * 520 + k0 + 8 + 2 * t);
            uint32_t b0r = wp[(kk * 8 + t) * 68 + 8 * w + g];
            uint32_t b1r = wp[(kk * 8 + t + 4) * 68 + 8 * w + g];
            if (kk & 1)
                asm volatile("mma.sync.aligned.m16n8k16.row.col.f32.f16.f16.f32 "
                             "{%0,%1,%2,%3}, {%4,%5,%6,%7}, {%8,%9}, {%0,%1,%2,%3};"
                             : "+f"(f0), "+f"(f1), "+f"(f2), "+f"(f3)
                             : "r"(a0), "r"(a1), "r"(a2), "r"(a3), "r"(b0r), "r"(b1r));
            else
                asm volatile("mma.sync.aligned.m16n8k16.row.col.f32.f16.f16.f32 "
                             "{%0,%1,%2,%3}, {%4,%5,%6,%7}, {%8,%9}, {%0,%1,%2,%3};"
                             : "+f"(e0), "+f"(e1), "+f"(e2), "+f"(e3)
                             : "r"(a0), "r"(a1), "r"(a2), "r"(a3), "r"(b0r), "r"(b1r));
        }
        float acc0 = e0 + f0, acc1 = e1 + f1, acc2 = e2 + f2, acc3 = e3 + f3;

        // ---- epilogue: x_new; write x_seq ----
        x0 = (1.f - ALPHA_N) * xp0 + ALPHA_N * (acc0 + brn0) + nz0.x;
        x1 = (1.f - ALPHA_N) * xp1 + ALPHA_N * (acc1 + brn1) + nz0.y;
        x2 = (1.f - ALPHA_N) * xp2 + ALPHA_N * (acc2 + brn0) + nz1.x;
        x3 = (1.f - ALPHA_N) * xp3 + ALPHA_N * (acc3 + brn1) + nz1.y;
        *reinterpret_cast<float2*>(&out_x[((size_t)br0 * T_STEPS + ts) * NH + hb]) = make_float2(x0, x1);
        *reinterpret_cast<float2*>(&out_x[((size_t)br1 * T_STEPS + ts) * NH + hb]) = make_float2(x2, x3);

        // ---- fused y partials: relu(x_new) @ w_out (reduce over t lanes) ----
        {
            float r0n = fmaxf(x0, 0.f), r1n = fmaxf(x1, 0.f);
            float r2n = fmaxf(x2, 0.f), r3n = fmaxf(x3, 0.f);
            float sA0 = r0n * wo00 + r1n * wo10;
            float sA1 = r0n * wo01 + r1n * wo11;
            float sA2 = r0n * wo02 + r1n * wo12;
            float sB0 = r2n * wo00 + r3n * wo10;
            float sB1 = r2n * wo01 + r3n * wo11;
            float sB2 = r2n * wo02 + r3n * wo12;
            #pragma unroll
            for (int off = 1; off <= 2; off <<= 1) {
                sA0 += __shfl_xor_sync(0xffffffffu, sA0, off);
                sA1 += __shfl_xor_sync(0xffffffffu, sA1, off);
                sA2 += __shfl_xor_sync(0xffffffffu, sA2, off);
                sB0 += __shfl_xor_sync(0xffffffffu, sB0, off);
                sB1 += __shfl_xor_sync(0xffffffffu, sB1, off);
                sB2 += __shfl_xor_sync(0xffffffffu, sB2, off);
            }
            if (t == 0) {
                ysm[g * 24 + w * 3 + 0] = sA0;
                ysm[g * 24 + w * 3 + 1] = sA1;
                ysm[g * 24 + w * 3 + 2] = sA2;
                ysm[(g + 8) * 24 + w * 3 + 0] = sB0;
                ysm[(g + 8) * 24 + w * 3 + 1] = sB1;
                ysm[(g + 8) * 24 + w * 3 + 2] = sB2;
            }
        }
        __syncthreads();
        if (tid < 48) {
            int row = tid / 3, o = tid - row * 3;
            float s = 0.f;
            #pragma unroll
            for (int ww = 0; ww < 8; ww++) s += ysm[row * 24 + ww * 3 + o];
            g_ypart[((((size_t)ts * 16 + grp) * 8 + slice) * 16 + row) * 3 + o] = s;
        }
    }
}

// ---------------- finalize y: slice-sum + softmax over batch ----------------
__global__ void __launch_bounds__(256) softmax_kernel(const float* __restrict__ b_out,
                                                      float* __restrict__ out_y)
{
    __shared__ float red[256];
    int ts = blockIdx.x;
    int b = threadIdx.x;
    int grp = b >> 4, row = b & 15;

    float v[NOUT], e[NOUT];
    #pragma unroll
    for (int o = 0; o < NOUT; o++) {
        float s = b_out[o];
        #pragma unroll
        for (int sl = 0; sl < 8; sl++)
            s += g_ypart[((((size_t)ts * 16 + grp) * 8 + sl) * 16 + row) * 3 + o];
        v[o] = s;
    }

    #pragma unroll
    for (int o = 0; o < NOUT; o++) {
        red[b] = v[o];
        __syncthreads();
        for (int s = 128; s > 0; s >>= 1) {
            if (b < s) red[b] = fmaxf(red[b], red[b + s]);
            __syncthreads();
        }
        float mx = red[0];
        __syncthreads();
        e[o] = expf(v[o] - mx);
        red[b] = e[o];
        __syncthreads();
        for (int s = 128; s > 0; s >>= 1) {
            if (b < s) red[b] += red[b + s];
            __syncthreads();
        }
        float sm = red[0];
        __syncthreads();
        out_y[((size_t)b * T_STEPS + ts) * NOUT + o] = e[o] / sm;
    }
}

// ---------------- launch ----------------------------------------------------
extern "C" void kernel_launch(void* const* d_in, const int* in_sizes, int n_in,
                              void* d_out, int out_size)
{
    const float* input_data = (const float*)d_in[0];
    const float* noise      = (const float*)d_in[1];
    const float* x_init     = (const float*)d_in[2];
    const float* syn_x_init = (const float*)d_in[3];
    const float* syn_u_init = (const float*)d_in[4];
    const float* w_in       = (const float*)d_in[5];
    const float* w_in_mask  = (const float*)d_in[6];
    const float* w_rnn_base = (const float*)d_in[7];
    const float* conn_mask  = (const float*)d_in[8];
    const float* ei_matrix  = (const float*)d_in[9];
    const float* b_rnn      = (const float*)d_in[10];
    const float* w_out      = (const float*)d_in[11];
    const float* w_out_mask = (const float*)d_in[12];
    const float* b_out      = (const float*)d_in[13];
    const float* a_std      = (const float*)d_in[14];
    const float* a_stf      = (const float*)d_in[15];
    const float* Uv         = (const float*)d_in[16];
    const float* dynv       = (const float*)d_in[17];

    float* out   = (float*)d_out;
    float* out_y = out;
    float* out_x = out + Y_SIZE;

    static bool attr_done = false;
    if (!attr_done) {
        cudaFuncSetAttribute(step_kernel, cudaFuncAttributeMaxDynamicSharedMemorySize, SMEM_STEP);
        attr_done = true;
    }

    prep_kernel<<<64, 256>>>(w_in, w_in_mask, w_rnn_base, conn_mask, ei_matrix,
                             w_out, w_out_mask);
    step_kernel<<<128, 256, SMEM_STEP>>>(input_data, noise, x_init, syn_x_init,
                                         syn_u_init, a_std, a_stf, Uv, dynv,
                                         b_rnn, out_x);
    softmax_kernel<<<T_STEPS, 256>>>(b_out, out_y);
}

// round 3
// speedup vs baseline: 2.1959x; 2.1959x over previous
#include <cuda_runtime.h>
#include <cuda_fp16.h>
#include <cstdint>

#define T_STEPS 300
#define BATCH   256
#define NIN     128
#define NH      512
#define NOUT    3
#define DTSEC   0.01f
#define ALPHA_N 0.2f

#define Y_SIZE (BATCH * T_STEPS * NOUT)

// ---------------- device scratch (static, allocation-free) ----------------
__device__ float     g_drive[(size_t)T_STEPS * BATCH * NH];   // 157 MB
__device__ uint32_t  g_wrnnp[(NH / 2) * NH];                  // packed half2 (k-pair x h)
__device__ uint32_t  g_winp[(NIN / 2) * NH];
__device__ float     g_wout[NH * NOUT];
__device__ __half    g_rpost[2 * BATCH * NH];                 // double-buffered activations
__device__ float     g_yraw[(size_t)T_STEPS * BATCH * NOUT];
__device__ unsigned  g_bar[16 * T_STEPS];                     // per (b-group, step) counters

__device__ __forceinline__ uint32_t smem_u32(const void* p) {
    uint32_t a;
    asm("{ .reg .u64 t; cvta.to.shared.u64 t, %1; cvt.u32.u64 %0, t; }" : "=r"(a) : "l"(p));
    return a;
}

// ---------------- prep -----------------------------------------------------
__global__ void prep_kernel(const float* __restrict__ w_in, const float* __restrict__ w_in_mask,
                            const float* __restrict__ w_rnn_base, const float* __restrict__ conn,
                            const float* __restrict__ ei, const float* __restrict__ w_out,
                            const float* __restrict__ w_out_mask)
{
    int tid = blockIdx.x * blockDim.x + threadIdx.x;
    int nth = gridDim.x * blockDim.x;

    for (int i = tid; i < (NH / 2) * NH; i += nth) {
        int p = i >> 9, h = i & (NH - 1);
        int k0 = 2 * p, k1 = 2 * p + 1;
        float s0 = ei[k0 * NH + k0];
        float s1 = ei[k1 * NH + k1];
        float v0 = fmaxf(w_rnn_base[k0 * NH + h] * conn[k0 * NH + h], 0.f) * s0;
        float v1 = fmaxf(w_rnn_base[k1 * NH + h] * conn[k1 * NH + h], 0.f) * s1;
        __half2 hv = __floats2half2_rn(v0, v1);
        g_wrnnp[i] = *reinterpret_cast<uint32_t*>(&hv);
    }
    for (int i = tid; i < (NIN / 2) * NH; i += nth) {
        int p = i >> 9, h = i & (NH - 1);
        float v0 = w_in[(2 * p) * NH + h] * w_in_mask[(2 * p) * NH + h];
        float v1 = w_in[(2 * p + 1) * NH + h] * w_in_mask[(2 * p + 1) * NH + h];
        __half2 hv = __floats2half2_rn(v0, v1);
        g_winp[i] = *reinterpret_cast<uint32_t*>(&hv);
    }
    for (int i = tid; i < NH * NOUT; i += nth)
        g_wout[i] = fmaxf(w_out[i] * w_out_mask[i], 0.f);
    for (int i = tid; i < 16 * T_STEPS; i += nth)
        g_bar[i] = 0u;
}

// ---------------- drive GEMM: drive = 0.2*(inp@w_in_eff + b_rnn) + noise ---
__global__ void __launch_bounds__(256) drive_gemm(const float* __restrict__ inp,
                                                  const float* __restrict__ noise,
                                                  const float* __restrict__ b_rnn)
{
    __shared__ __half   a_s[64 * 136];
    __shared__ uint32_t b_s[64 * 68];

    int row0 = blockIdx.x * 64;
    int n0   = blockIdx.y * 64;
    int tid  = threadIdx.x;

    #pragma unroll
    for (int j = 0; j < 32; j++) {
        int idx = tid + j * 256;
        int i = idx >> 7, k = idx & 127;
        a_s[i * 136 + k] = __float2half_rn(inp[(size_t)(row0 + i) * NIN + k]);
    }
    #pragma unroll
    for (int j = 0; j < 16; j++) {
        int idx = tid + j * 256;
        int p = idx >> 6, c = idx & 63;
        b_s[p * 68 + c] = g_winp[p * NH + n0 + c];
    }
    __syncthreads();

    int w = tid >> 5, lane = tid & 31;
    int g = lane >> 2, t = lane & 3;
    int m0 = (w & 3) * 16;
    int nw = (w >> 2) * 32;

    float acc[4][4] = {};
    #pragma unroll
    for (int kk = 0; kk < 8; kk++) {
        int k0 = kk * 16;
        uint32_t a0 = *reinterpret_cast<const uint32_t*>(&a_s[(m0 + g) * 136 + k0 + 2 * t]);
        uint32_t a1 = *reinterpret_cast<const uint32_t*>(&a_s[(m0 + g + 8) * 136 + k0 + 2 * t]);
        uint32_t a2 = *reinterpret_cast<const uint32_t*>(&a_s[(m0 + g) * 136 + k0 + 8 + 2 * t]);
        uint32_t a3 = *reinterpret_cast<const uint32_t*>(&a_s[(m0 + g + 8) * 136 + k0 + 8 + 2 * t]);
        #pragma unroll
        for (int s = 0; s < 4; s++) {
            int col = nw + 8 * s + g;
            uint32_t b0 = b_s[(kk * 8 + t) * 68 + col];
            uint32_t b1 = b_s[(kk * 8 + t + 4) * 68 + col];
            asm volatile("mma.sync.aligned.m16n8k16.row.col.f32.f16.f16.f32 "
                         "{%0,%1,%2,%3}, {%4,%5,%6,%7}, {%8,%9}, {%0,%1,%2,%3};"
                         : "+f"(acc[s][0]), "+f"(acc[s][1]), "+f"(acc[s][2]), "+f"(acc[s][3])
                         : "r"(a0), "r"(a1), "r"(a2), "r"(a3), "r"(b0), "r"(b1));
        }
    }

    #pragma unroll
    for (int s = 0; s < 4; s++) {
        int gc  = n0 + nw + 8 * s + 2 * t;
        float br0 = b_rnn[gc], br1 = b_rnn[gc + 1];
        int r0 = row0 + m0 + g;
        int r1 = r0 + 8;
        float2 nz0 = *reinterpret_cast<const float2*>(&noise[(size_t)r0 * NH + gc]);
        float2 nz1 = *reinterpret_cast<const float2*>(&noise[(size_t)r1 * NH + gc]);
        float2 d0, d1;
        d0.x = ALPHA_N * (acc[s][0] + br0) + nz0.x;
        d0.y = ALPHA_N * (acc[s][1] + br1) + nz0.y;
        d1.x = ALPHA_N * (acc[s][2] + br0) + nz1.x;
        d1.y = ALPHA_N * (acc[s][3] + br1) + nz1.y;
        *reinterpret_cast<float2*>(&g_drive[(size_t)r0 * NH + gc]) = d0;
        *reinterpret_cast<float2*>(&g_drive[(size_t)r1 * NH + gc]) = d1;
    }
}

// ---------------- persistent step kernel -----------------------------------
// 128 CTAs = 16 b-groups x 8 h-slices. W_rnn B-fragments in registers,
// A-fragments via ldmatrix, REDG-release barrier, drive prefetched.
__global__ void __launch_bounds__(256, 1) step_kernel(
    const float* __restrict__ x_init, const float* __restrict__ sx_init,
    const float* __restrict__ su_init,
    const float* __restrict__ a_std, const float* __restrict__ a_stf,
    const float* __restrict__ Uv, const float* __restrict__ dynv,
    float* __restrict__ out_x)
{
    __shared__ __half rp[16 * 520];      // staged rpost tile [16][520]

    int cta   = blockIdx.x;
    int grp   = cta >> 3;
    int slice = cta & 7;
    int b0 = grp * 16;
    int h0 = slice * 64;
    int tid = threadIdx.x;
    int w = tid >> 5, lane = tid & 31;
    int g = lane >> 2, t = lane & 3;

    // ---- persistent B fragments for W_rnn slice (registers, step-invariant)
    uint32_t breg0[32], breg1[32];
    {
        int c = h0 + 8 * w + g;
        #pragma unroll
        for (int kk = 0; kk < 32; kk++) {
            breg0[kk] = g_wrnnp[(size_t)(kk * 8 + t) * NH + c];
            breg1[kk] = g_wrnnp[(size_t)(kk * 8 + t + 4) * NH + c];
        }
    }

    int hb  = h0 + 8 * w + 2 * t;
    int br0 = b0 + g, br1 = b0 + g + 8;

    float as0 = a_std[hb], as1 = a_std[hb + 1];
    float af0 = a_stf[hb], af1 = a_stf[hb + 1];
    float U0  = Uv[hb],    U1  = Uv[hb + 1];
    float dy0 = dynv[hb],  dy1 = dynv[hb + 1];

    float x0 = x_init[br0 * NH + hb],   x1 = x_init[br0 * NH + hb + 1];
    float x2 = x_init[br1 * NH + hb],   x3 = x_init[br1 * NH + hb + 1];
    float sx0 = sx_init[br0 * NH + hb], sx1 = sx_init[br0 * NH + hb + 1];
    float sx2 = sx_init[br1 * NH + hb], sx3 = sx_init[br1 * NH + hb + 1];
    float su0 = su_init[br0 * NH + hb], su1 = su_init[br0 * NH + hb + 1];
    float su2 = su_init[br1 * NH + hb], su3 = su_init[br1 * NH + hb + 1];

    __half2* rgl = reinterpret_cast<__half2*>(g_rpost);

    // ldmatrix lane address: row = lane&15, k-half offset for lanes 16-31
    uint32_t lds_a = smem_u32(rp) + (lane & 15) * (520 * 2) + ((lane >> 4) & 1) * 16;

    for (int ts = 0; ts < T_STEPS; ts++) {
        // ---- prefetch drive early (consumed after MMA ~1500cy later) ----
        float2 d0 = *reinterpret_cast<const float2*>(&g_drive[((size_t)ts * BATCH + br0) * NH + hb]);
        float2 d1 = *reinterpret_cast<const float2*>(&g_drive[((size_t)ts * BATCH + br1) * NH + hb]);

        // ---- phase 1: STP update + x_post + rpost ----
        float xp0, xp1, xp2, xp3;
        {
            float r, sxn, sun;
            r = fmaxf(x0, 0.f);
            sxn = sx0 + (as0 * (1.f - sx0) - DTSEC * su0 * sx0 * r) * dy0;
            sun = su0 + (af0 * (U0 - su0) + DTSEC * U0 * (1.f - su0) * r) * dy0;
            sx0 = fminf(fmaxf(sxn, 0.f), 1.f); su0 = fminf(fmaxf(sun, 0.f), 1.f);
            xp0 = su0 * sx0 * x0;

            r = fmaxf(x1, 0.f);
            sxn = sx1 + (as1 * (1.f - sx1) - DTSEC * su1 * sx1 * r) * dy1;
            sun = su1 + (af1 * (U1 - su1) + DTSEC * U1 * (1.f - su1) * r) * dy1;
            sx1 = fminf(fmaxf(sxn, 0.f), 1.f); su1 = fminf(fmaxf(sun, 0.f), 1.f);
            xp1 = su1 * sx1 * x1;

            r = fmaxf(x2, 0.f);
            sxn = sx2 + (as0 * (1.f - sx2) - DTSEC * su2 * sx2 * r) * dy0;
            sun = su2 + (af0 * (U0 - su2) + DTSEC * U0 * (1.f - su2) * r) * dy0;
            sx2 = fminf(fmaxf(sxn, 0.f), 1.f); su2 = fminf(fmaxf(sun, 0.f), 1.f);
            xp2 = su2 * sx2 * x2;

            r = fmaxf(x3, 0.f);
            sxn = sx3 + (as1 * (1.f - sx3) - DTSEC * su3 * sx3 * r) * dy1;
            sun = su3 + (af1 * (U1 - su3) + DTSEC * U1 * (1.f - su3) * r) * dy1;
            sx3 = fminf(fmaxf(sxn, 0.f), 1.f); su3 = fminf(fmaxf(sun, 0.f), 1.f);
            xp3 = su3 * sx3 * x3;
        }
        int buf = ts & 1;
        rgl[(buf * BATCH * NH + br0 * NH + hb) >> 1] =
            __floats2half2_rn(fmaxf(xp0, 0.f), fmaxf(xp1, 0.f));
        rgl[(buf * BATCH * NH + br1 * NH + hb) >> 1] =
            __floats2half2_rn(fmaxf(xp2, 0.f), fmaxf(xp3, 0.f));

        // ---- group barrier: REDG release + acquire poll ----
        __syncthreads();
        if (tid == 0) {
            unsigned* c = &g_bar[grp * T_STEPS + ts];
            asm volatile("red.release.gpu.global.add.u32 [%0], %1;" :: "l"(c), "r"(1u) : "memory");
            unsigned v;
            do {
                asm volatile("ld.acquire.gpu.global.u32 %0, [%1];" : "=r"(v) : "l"(c) : "memory");
            } while (v < 8u);
        }
        __syncthreads();

        // ---- stage rpost [16][512] fp16 via L2 (.cg skips L1) ----
        {
            const uint4* src = reinterpret_cast<const uint4*>(g_rpost + buf * BATCH * NH);
            #pragma unroll
            for (int j = 0; j < 4; j++) {
                int idx = tid + j * 256;
                int row = idx >> 6, c8 = idx & 63;
                uint4 v;
                asm volatile("ld.global.cg.v4.u32 {%0,%1,%2,%3}, [%4];"
                             : "=r"(v.x), "=r"(v.y), "=r"(v.z), "=r"(v.w)
                             : "l"(src + (size_t)(b0 + row) * 64 + c8));
                *reinterpret_cast<uint4*>(rp + row * 520 + c8 * 8) = v;
            }
        }
        __syncthreads();

        // ---- mma: C[16x64] = rpost[16x512] @ W[512x64], B in regs ----
        float e0 = 0.f, e1 = 0.f, e2 = 0.f, e3 = 0.f;
        float f0 = 0.f, f1 = 0.f, f2 = 0.f, f3 = 0.f;
        #pragma unroll
        for (int kk = 0; kk < 32; kk++) {
            uint32_t a0, a1, a2, a3;
            asm volatile("ldmatrix.sync.aligned.m8n8.x4.shared.b16 {%0,%1,%2,%3}, [%4];"
                         : "=r"(a0), "=r"(a1), "=r"(a2), "=r"(a3)
                         : "r"(lds_a + kk * 32));
            if (kk & 1)
                asm volatile("mma.sync.aligned.m16n8k16.row.col.f32.f16.f16.f32 "
                             "{%0,%1,%2,%3}, {%4,%5,%6,%7}, {%8,%9}, {%0,%1,%2,%3};"
                             : "+f"(f0), "+f"(f1), "+f"(f2), "+f"(f3)
                             : "r"(a0), "r"(a1), "r"(a2), "r"(a3), "r"(breg0[kk]), "r"(breg1[kk]));
            else
                asm volatile("mma.sync.aligned.m16n8k16.row.col.f32.f16.f16.f32 "
                             "{%0,%1,%2,%3}, {%4,%5,%6,%7}, {%8,%9}, {%0,%1,%2,%3};"
                             : "+f"(e0), "+f"(e1), "+f"(e2), "+f"(e3)
                             : "r"(a0), "r"(a1), "r"(a2), "r"(a3), "r"(breg0[kk]), "r"(breg1[kk]));
        }

        // ---- epilogue: x_new = 0.8*x_post + 0.2*acc + drive; store x_seq ----
        x0 = (1.f - ALPHA_N) * xp0 + ALPHA_N * (e0 + f0) + d0.x;
        x1 = (1.f - ALPHA_N) * xp1 + ALPHA_N * (e1 + f1) + d0.y;
        x2 = (1.f - ALPHA_N) * xp2 + ALPHA_N * (e2 + f2) + d1.x;
        x3 = (1.f - ALPHA_N) * xp3 + ALPHA_N * (e3 + f3) + d1.y;
        *reinterpret_cast<float2*>(&out_x[((size_t)br0 * T_STEPS + ts) * NH + hb]) = make_float2(x0, x1);
        *reinterpret_cast<float2*>(&out_x[((size_t)br1 * T_STEPS + ts) * NH + hb]) = make_float2(x2, x3);
        // NOTE: no trailing sync needed — next step's first __syncthreads
        // (before the barrier) already guards rp reuse.
    }
}

// ---------------- y = relu(x) @ w_out_eff + b_out --------------------------
__global__ void __launch_bounds__(256) y_kernel(const float* __restrict__ out_x,
                                                const float* __restrict__ b_out)
{
    __shared__ float wsh[NH * NOUT];
    for (int i = threadIdx.x; i < NH * NOUT; i += 256) wsh[i] = g_wout[i];
    __syncthreads();

    int w = threadIdx.x >> 5, lane = threadIdx.x & 31;
    int row = blockIdx.x * 8 + w;           // t*256 + b
    int t = row >> 8;
    int b = row & 255;
    const float* xr = out_x + ((size_t)b * T_STEPS + t) * NH;

    float a0 = 0.f, a1 = 0.f, a2 = 0.f;
    #pragma unroll 4
    for (int h = lane; h < NH; h += 32) {
        float r = fmaxf(xr[h], 0.f);
        a0 += r * wsh[h * 3 + 0];
        a1 += r * wsh[h * 3 + 1];
        a2 += r * wsh[h * 3 + 2];
    }
    #pragma unroll
    for (int off = 16; off > 0; off >>= 1) {
        a0 += __shfl_xor_sync(0xffffffffu, a0, off);
        a1 += __shfl_xor_sync(0xffffffffu, a1, off);
        a2 += __shfl_xor_sync(0xffffffffu, a2, off);
    }
    if (lane == 0) {
        size_t base = ((size_t)t * BATCH + b) * NOUT;
        g_yraw[base + 0] = a0 + b_out[0];
        g_yraw[base + 1] = a1 + b_out[1];
        g_yraw[base + 2] = a2 + b_out[2];
    }
}

// ---------------- softmax over batch axis ----------------------------------
__global__ void __launch_bounds__(256) softmax_kernel(float* __restrict__ out_y)
{
    __shared__ float red[256];
    int t = blockIdx.x;
    int b = threadIdx.x;
    float v[NOUT], e[NOUT];
    #pragma unroll
    for (int o = 0; o < NOUT; o++)
        v[o] = g_yraw[((size_t)t * BATCH + b) * NOUT + o];

    #pragma unroll
    for (int o = 0; o < NOUT; o++) {
        red[b] = v[o];
        __syncthreads();
        for (int s = 128; s > 0; s >>= 1) {
            if (b < s) red[b] = fmaxf(red[b], red[b + s]);
            __syncthreads();
        }
        float mx = red[0];
        __syncthreads();
        e[o] = expf(v[o] - mx);
        red[b] = e[o];
        __syncthreads();
        for (int s = 128; s > 0; s >>= 1) {
            if (b < s) red[b] += red[b + s];
            __syncthreads();
        }
        float sm = red[0];
        __syncthreads();
        out_y[((size_t)b * T_STEPS + t) * NOUT + o] = e[o] / sm;
    }
}

// ---------------- launch ----------------------------------------------------
extern "C" void kernel_launch(void* const* d_in, const int* in_sizes, int n_in,
                              void* d_out, int out_size)
{
    const float* input_data = (const float*)d_in[0];
    const float* noise      = (const float*)d_in[1];
    const float* x_init     = (const float*)d_in[2];
    const float* syn_x_init = (const float*)d_in[3];
    const float* syn_u_init = (const float*)d_in[4];
    const float* w_in       = (const float*)d_in[5];
    const float* w_in_mask  = (const float*)d_in[6];
    const float* w_rnn_base = (const float*)d_in[7];
    const float* conn_mask  = (const float*)d_in[8];
    const float* ei_matrix  = (const float*)d_in[9];
    const float* b_rnn      = (const float*)d_in[10];
    const float* w_out      = (const float*)d_in[11];
    const float* w_out_mask = (const float*)d_in[12];
    const float* b_out      = (const float*)d_in[13];
    const float* a_std      = (const float*)d_in[14];
    const float* a_stf      = (const float*)d_in[15];
    const float* Uv         = (const float*)d_in[16];
    const float* dynv       = (const float*)d_in[17];

    float* out   = (float*)d_out;
    float* out_y = out;
    float* out_x = out + Y_SIZE;

    prep_kernel<<<148, 256>>>(w_in, w_in_mask, w_rnn_base, conn_mask, ei_matrix,
                              w_out, w_out_mask);
    dim3 dgrid(76800 / 64, NH / 64);
    drive_gemm<<<dgrid, 256>>>(input_data, noise, b_rnn);
    step_kernel<<<128, 256>>>(x_init, syn_x_init, syn_u_init,
                              a_std, a_stf, Uv, dynv, out_x);
    y_kernel<<<76800 / 8, 256>>>(out_x, b_out);
    softmax_kernel<<<T_STEPS, 256>>>(out_y);
}